// round 8
// baseline (speedup 1.0000x reference)
#include <cuda_runtime.h>
#include <cstddef>

#define NN 64
#define G  32          // batches per block (one warp lane per batch)
#define TB 256         // 8 role-warps
#define BT 16384       // total batches

// global scratch (coalesced [n][b]) — only vectors, no matrices
__device__ float4 gvL[NN * BT];        // normalized prefix vectors, n = 1..63
__device__ float4 gvR[NN * BT];        // normalized suffix vectors, n = 0..62

__device__ __forceinline__ float nan0(float h) {
    unsigned u = __float_as_uint(h);
    return ((u & 0x7fffffffu) > 0x7f800000u) ? 0.0f : h;
}

// dynamic smem layout (floats)
#define SA_OFF   0                          // [NN*32]                2048
#define SB_OFF   2048                       // [NN*68]                4352
#define SX_OFF   (SB_OFF + 4352)            // [G*65] float2          4160
#define SQ16_OFF (SX_OFF + 4160)            // [G] float4              128
#define ST48_OFF (SQ16_OFF + 128)           // [G] float4              128
#define SP1_OFF  (ST48_OFF + 128)           // [4*G] float4 rows       512
#define SP2_OFF  (SP1_OFF + 512)            // [4*G] float4            512
#define SQ1_OFF  (SP2_OFF + 512)            // [4*G] float4            512
#define SQ2_OFF  (SQ1_OFF + 512)            // [4*G] float4            512
#define SMEM_FLOATS (SQ2_OFF + 512)         // 12872 floats = 51488 B

__global__ __launch_bounds__(TB, 4)
void tdvp_kernel(const float* __restrict__ xg, const float* __restrict__ Ag,
                 const float* __restrict__ Bg, const float* __restrict__ sg,
                 float* __restrict__ yg)
{
    extern __shared__ float sm[];
    float*  sA   = sm + SA_OFF;
    float*  sB   = sm + SB_OFF;
    float2* sx   = (float2*)(sm + SX_OFF);
    float4* sQ16 = (float4*)(sm + SQ16_OFF);   // raw q16 per batch
    float4* sT48 = (float4*)(sm + ST48_OFF);   // raw t48 per batch
    float4* sP1  = (float4*)(sm + SP1_OFF);    // P1 = M[16..31], rows at [c*G+g]
    float4* sP2  = (float4*)(sm + SP2_OFF);    // P2 = M[32..47]
    float4* sQ1  = (float4*)(sm + SQ1_OFF);    // Q1 = M[33..48]
    float4* sQ2  = (float4*)(sm + SQ2_OFF);    // Q2 = M[17..32]

    const int tid = threadIdx.x;
    const int b0  = blockIdx.x * G;

    for (int i = tid; i < NN * 32; i += TB) sA[i] = Ag[i];
    for (int i = tid; i < NN * 64; i += TB) sB[(i >> 6) * 68 + (i & 63)] = Bg[i];
    const float2* xv = (const float2*)xg;
    for (int idx = tid; idx < G * NN; idx += TB) {
        float2 v = xv[(size_t)b0 * NN + idx];
        float inv = rsqrtf(v.x * v.x + v.y * v.y);
        v.x *= inv; v.y *= inv;
        sx[(idx >> 6) * 65 + (idx & 63)] = v;
    }
    __syncthreads();

    const int g = tid & 31;
    const int r = tid >> 5;    // 0-3 fwd roles, 4-7 bwd roles
    const int b = b0 + g;

    #define BUILD_M4(nn, R0_, R1_, R2_, R3_)                                   \
    {                                                                          \
        float2 xn_ = sx[g * 65 + (nn)];                                        \
        const float4* ap_ = (const float4*)(sA + (nn) * 32);                   \
        float4 q0_ = ap_[0], q1_ = ap_[1], q2_ = ap_[2], q3_ = ap_[3];         \
        float4 q4_ = ap_[4], q5_ = ap_[5], q6_ = ap_[6], q7_ = ap_[7];         \
        R0_ = make_float4(fmaf(q0_.x, xn_.x, q0_.y * xn_.y),                   \
                          fmaf(q0_.z, xn_.x, q0_.w * xn_.y),                   \
                          fmaf(q1_.x, xn_.x, q1_.y * xn_.y),                   \
                          fmaf(q1_.z, xn_.x, q1_.w * xn_.y));                  \
        R1_ = make_float4(fmaf(q2_.x, xn_.x, q2_.y * xn_.y),                   \
                          fmaf(q2_.z, xn_.x, q2_.w * xn_.y),                   \
                          fmaf(q3_.x, xn_.x, q3_.y * xn_.y),                   \
                          fmaf(q3_.z, xn_.x, q3_.w * xn_.y));                  \
        R2_ = make_float4(fmaf(q4_.x, xn_.x, q4_.y * xn_.y),                   \
                          fmaf(q4_.z, xn_.x, q4_.w * xn_.y),                   \
                          fmaf(q5_.x, xn_.x, q5_.y * xn_.y),                   \
                          fmaf(q5_.z, xn_.x, q5_.w * xn_.y));                  \
        R3_ = make_float4(fmaf(q6_.x, xn_.x, q6_.y * xn_.y),                   \
                          fmaf(q6_.z, xn_.x, q6_.w * xn_.y),                   \
                          fmaf(q7_.x, xn_.x, q7_.y * xn_.y),                   \
                          fmaf(q7_.z, xn_.x, q7_.w * xn_.y));                  \
    }

    // d = v * [M rows] (row-vector x matrix)
    #define VMAT(d, v_, M0, M1, M2, M3)                                        \
        d.x = fmaf(v_.x, M0.x, v_.y * M1.x) + fmaf(v_.z, M2.x, v_.w * M3.x);   \
        d.y = fmaf(v_.x, M0.y, v_.y * M1.y) + fmaf(v_.z, M2.y, v_.w * M3.y);   \
        d.z = fmaf(v_.x, M0.z, v_.y * M1.z) + fmaf(v_.z, M2.z, v_.w * M3.z);   \
        d.w = fmaf(v_.x, M0.w, v_.y * M1.w) + fmaf(v_.z, M2.w, v_.w * M3.w);

    // d = [M rows] * w (matrix x column-vector)
    #define MATV(d, M0, M1, M2, M3, w_)                                        \
        d.x = fmaf(M0.x, w_.x, M0.y * w_.y) + fmaf(M0.z, w_.z, M0.w * w_.w);   \
        d.y = fmaf(M1.x, w_.x, M1.y * w_.y) + fmaf(M1.z, w_.z, M1.w * w_.w);   \
        d.z = fmaf(M2.x, w_.x, M2.y * w_.y) + fmaf(M2.z, w_.z, M2.w * w_.w);   \
        d.w = fmaf(M3.x, w_.x, M3.y * w_.y) + fmaf(M3.z, w_.z, M3.w * w_.w);

    #define STORE_NORM_L(nn, v_)                                               \
    {                                                                          \
        float d_ = v_.x*v_.x + v_.y*v_.y + v_.z*v_.z + v_.w*v_.w;              \
        float i_ = 1.0f / (sqrtf(d_) + 1e-6f);                                 \
        gvL[(nn) * BT + b] = make_float4(v_.x*i_, v_.y*i_, v_.z*i_, v_.w*i_);  \
    }
    #define STORE_NORM_R(nn, v_)                                               \
    {                                                                          \
        float d_ = v_.x*v_.x + v_.y*v_.y + v_.z*v_.z + v_.w*v_.w;              \
        float i_ = 1.0f / (sqrtf(d_) + 1e-6f);                                 \
        gvR[(nn) * BT + b] = make_float4(v_.x*i_, v_.y*i_, v_.z*i_, v_.w*i_);  \
    }

    // ================= phase 1 =================
    if (r == 0) {
        // fwd vec: n = 1..16, raw q16 -> smem
        float4 v = make_float4(1.f, 0.f, 0.f, 0.f);
        #pragma unroll 1
        for (int n = 1; n <= 16; ++n) {
            float4 M0, M1, M2, M3;
            BUILD_M4(n - 1, M0, M1, M2, M3);
            float4 t; VMAT(t, v, M0, M1, M2, M3); v = t;
            STORE_NORM_L(n, v);
        }
        sQ16[g] = v;
    } else if (r == 1) {
        // P1 = M[16..31]
        float4 P0, P1, P2, P3;
        BUILD_M4(16, P0, P1, P2, P3);
        #pragma unroll 1
        for (int j = 17; j <= 31; ++j) {
            float4 M0, M1, M2, M3;
            BUILD_M4(j, M0, M1, M2, M3);
            float4 t;
            VMAT(t, P0, M0, M1, M2, M3); P0 = t;
            VMAT(t, P1, M0, M1, M2, M3); P1 = t;
            VMAT(t, P2, M0, M1, M2, M3); P2 = t;
            VMAT(t, P3, M0, M1, M2, M3); P3 = t;
        }
        sP1[0*G+g] = P0; sP1[1*G+g] = P1; sP1[2*G+g] = P2; sP1[3*G+g] = P3;
    } else if (r == 2) {
        // P2 = M[32..47]
        float4 P0, P1, P2, P3;
        BUILD_M4(32, P0, P1, P2, P3);
        #pragma unroll 1
        for (int j = 33; j <= 47; ++j) {
            float4 M0, M1, M2, M3;
            BUILD_M4(j, M0, M1, M2, M3);
            float4 t;
            VMAT(t, P0, M0, M1, M2, M3); P0 = t;
            VMAT(t, P1, M0, M1, M2, M3); P1 = t;
            VMAT(t, P2, M0, M1, M2, M3); P2 = t;
            VMAT(t, P3, M0, M1, M2, M3); P3 = t;
        }
        sP2[0*G+g] = P0; sP2[1*G+g] = P1; sP2[2*G+g] = P2; sP2[3*G+g] = P3;
    } else if (r == 4) {
        // bwd vec: n = 62..48, raw t48 -> smem
        float4 w = make_float4(1.f, 0.f, 0.f, 0.f);
        #pragma unroll 1
        for (int n = 62; n >= 48; --n) {
            float4 M0, M1, M2, M3;
            BUILD_M4(n + 1, M0, M1, M2, M3);
            float4 t; MATV(t, M0, M1, M2, M3, w); w = t;
            STORE_NORM_R(n, w);
        }
        sT48[g] = w;
    } else if (r == 5) {
        // Q1 = M[33..48] (prepend: Q = M[j]*Q)
        float4 Q0, Q1, Q2, Q3;
        BUILD_M4(48, Q0, Q1, Q2, Q3);
        #pragma unroll 1
        for (int j = 47; j >= 33; --j) {
            float4 M0, M1, M2, M3;
            BUILD_M4(j, M0, M1, M2, M3);
            float4 T0, T1, T2, T3;
            VMAT(T0, M0, Q0, Q1, Q2, Q3);
            VMAT(T1, M1, Q0, Q1, Q2, Q3);
            VMAT(T2, M2, Q0, Q1, Q2, Q3);
            VMAT(T3, M3, Q0, Q1, Q2, Q3);
            Q0 = T0; Q1 = T1; Q2 = T2; Q3 = T3;
        }
        sQ1[0*G+g] = Q0; sQ1[1*G+g] = Q1; sQ1[2*G+g] = Q2; sQ1[3*G+g] = Q3;
    } else if (r == 6) {
        // Q2 = M[17..32]
        float4 Q0, Q1, Q2, Q3;
        BUILD_M4(32, Q0, Q1, Q2, Q3);
        #pragma unroll 1
        for (int j = 31; j >= 17; --j) {
            float4 M0, M1, M2, M3;
            BUILD_M4(j, M0, M1, M2, M3);
            float4 T0, T1, T2, T3;
            VMAT(T0, M0, Q0, Q1, Q2, Q3);
            VMAT(T1, M1, Q0, Q1, Q2, Q3);
            VMAT(T2, M2, Q0, Q1, Q2, Q3);
            VMAT(T3, M3, Q0, Q1, Q2, Q3);
            Q0 = T0; Q1 = T1; Q2 = T2; Q3 = T3;
        }
        sQ2[0*G+g] = Q0; sQ2[1*G+g] = Q1; sQ2[2*G+g] = Q2; sQ2[3*G+g] = Q3;
    }
    __syncthreads();

    // ================= phase 2 + 3: boundary derivation + segment rewalk =================
    if (r == 1) {
        float4 v = sQ16[g];                      // raw q16
        #pragma unroll 1
        for (int n = 17; n <= 32; ++n) {
            float4 M0, M1, M2, M3;
            BUILD_M4(n - 1, M0, M1, M2, M3);
            float4 t; VMAT(t, v, M0, M1, M2, M3); v = t;
            STORE_NORM_L(n, v);
        }
    } else if (r == 2) {
        float4 q = sQ16[g];
        float4 R0 = sP1[0*G+g], R1 = sP1[1*G+g], R2 = sP1[2*G+g], R3 = sP1[3*G+g];
        float4 v; VMAT(v, q, R0, R1, R2, R3);    // raw q32
        #pragma unroll 1
        for (int n = 33; n <= 48; ++n) {
            float4 M0, M1, M2, M3;
            BUILD_M4(n - 1, M0, M1, M2, M3);
            float4 t; VMAT(t, v, M0, M1, M2, M3); v = t;
            STORE_NORM_L(n, v);
        }
    } else if (r == 3) {
        float4 q = sQ16[g];
        float4 R0 = sP1[0*G+g], R1 = sP1[1*G+g], R2 = sP1[2*G+g], R3 = sP1[3*G+g];
        float4 q32; VMAT(q32, q, R0, R1, R2, R3);
        R0 = sP2[0*G+g]; R1 = sP2[1*G+g]; R2 = sP2[2*G+g]; R3 = sP2[3*G+g];
        float4 v; VMAT(v, q32, R0, R1, R2, R3);  // raw q48
        #pragma unroll 1
        for (int n = 49; n <= 63; ++n) {
            float4 M0, M1, M2, M3;
            BUILD_M4(n - 1, M0, M1, M2, M3);
            float4 t; VMAT(t, v, M0, M1, M2, M3); v = t;
            STORE_NORM_L(n, v);
        }
    } else if (r == 5) {
        float4 w = sT48[g];                      // raw t48
        #pragma unroll 1
        for (int n = 47; n >= 32; --n) {
            float4 M0, M1, M2, M3;
            BUILD_M4(n + 1, M0, M1, M2, M3);
            float4 t; MATV(t, M0, M1, M2, M3, w); w = t;
            STORE_NORM_R(n, w);
        }
    } else if (r == 6) {
        float4 t48 = sT48[g];
        float4 R0 = sQ1[0*G+g], R1 = sQ1[1*G+g], R2 = sQ1[2*G+g], R3 = sQ1[3*G+g];
        float4 w; MATV(w, R0, R1, R2, R3, t48);  // raw t32
        #pragma unroll 1
        for (int n = 31; n >= 16; --n) {
            float4 M0, M1, M2, M3;
            BUILD_M4(n + 1, M0, M1, M2, M3);
            float4 t; MATV(t, M0, M1, M2, M3, w); w = t;
            STORE_NORM_R(n, w);
        }
    } else if (r == 7) {
        float4 t48 = sT48[g];
        float4 R0 = sQ1[0*G+g], R1 = sQ1[1*G+g], R2 = sQ1[2*G+g], R3 = sQ1[3*G+g];
        float4 t32; MATV(t32, R0, R1, R2, R3, t48);
        R0 = sQ2[0*G+g]; R1 = sQ2[1*G+g]; R2 = sQ2[2*G+g]; R3 = sQ2[3*G+g];
        float4 w; MATV(w, R0, R1, R2, R3, t32);  // raw t16
        #pragma unroll 1
        for (int n = 15; n >= 0; --n) {
            float4 M0, M1, M2, M3;
            BUILD_M4(n + 1, M0, M1, M2, M3);
            float4 t; MATV(t, M0, M1, M2, M3, w); w = t;
            STORE_NORM_R(n, w);
        }
    }
    __syncthreads();

    // ================= output phase: n = r + 8k =================
    {
        const float s = sg[0];
        #pragma unroll 1
        for (int k = 0; k < 8; ++k) {
            const int n = r + 8 * k;

            float4 u = (n == 0)      ? make_float4(1.f, 0.f, 0.f, 0.f) : gvL[n * BT + b];
            float4 a = (n == NN - 1) ? make_float4(1.f, 0.f, 0.f, 0.f) : gvR[n * BT + b];

            float uu[4] = {u.x, u.y, u.z, u.w};
            float aa[4] = {a.x, a.y, a.z, a.w};
            float H0 = 0.f, H1 = 0.f, H2 = 0.f, H3 = 0.f;
            const float* bb = sB + n * 68;
            #pragma unroll
            for (int i = 0; i < 4; ++i) {
                #pragma unroll
                for (int l = 0; l < 4; ++l) {
                    float w = uu[i] * aa[l];
                    float4 bv = *(const float4*)(bb + i * 16 + l * 4);  // broadcast
                    H0 = fmaf(w, bv.x, H0);
                    H1 = fmaf(w, bv.y, H1);
                    H2 = fmaf(w, bv.z, H2);
                    H3 = fmaf(w, bv.w, H3);
                }
            }

            float f    = sqrtf(H0*H0 + H1*H1 + H2*H2 + H3*H3);
            float invf = s / (f + 1e-6f);
            H0 = fmaxf(nan0(H0 * invf), 0.f);
            H1 = fmaxf(nan0(H1 * invf), 0.f);
            H2 = fmaxf(nan0(H2 * invf), 0.f);
            H3 = fmaxf(nan0(H3 * invf), 0.f);

            float2 xn = sx[g * 65 + n];
            float y0 = fmaf(H0, xn.x, H1 * xn.y);
            float y1 = fmaf(H2, xn.x, H3 * xn.y);
            sx[g * 65 + n] = make_float2(y0, y1);
        }
    }
    __syncthreads();

    float2* yv = (float2*)yg;
    for (int idx = tid; idx < G * NN; idx += TB)
        yv[(size_t)b0 * NN + idx] = sx[(idx >> 6) * 65 + (idx & 63)];
}

extern "C" void kernel_launch(void* const* d_in, const int* in_sizes, int n_in,
                              void* d_out, int out_size) {
    const float* x = (const float*)d_in[0];
    const float* A = (const float*)d_in[1];
    const float* B = (const float*)d_in[2];
    const float* s = (const float*)d_in[3];
    float* y = (float*)d_out;

    const int batch = in_sizes[0] / (NN * 2);   // 16384
    const int grid  = batch / G;                // 512
    const size_t smem = (size_t)SMEM_FLOATS * sizeof(float);

    cudaFuncSetAttribute(tdvp_kernel, cudaFuncAttributeMaxDynamicSharedMemorySize, (int)smem);
    tdvp_kernel<<<grid, TB, smem>>>(x, A, B, s, y);
}

// round 9
// speedup vs baseline: 1.3380x; 1.3380x over previous
#include <cuda_runtime.h>
#include <cstddef>

#define NN 64
#define G  16          // batches per block (half-warp lanes)
#define TB 256         // 16 half-warp roles
#define BT 16384       // total batches

// global scratch (L2-resident), coalesced [n][b]
__device__ float4 gvL[NN * BT];   // normalized prefix vectors, n = 1..63
__device__ float4 gvR[NN * BT];   // normalized suffix vectors, n = 0..62

// smem float offsets
#define SA_   0                    // A original       [64*32] = 2048
#define SAT_  2048                 // A transposed     [64*32] = 2048
#define SXX_  4096                 // xn.x [64*17]             = 1088
#define SXY_  (SXX_ + 1088)        // xn.y [64*17]             = 1088
#define SU_   (SXY_ + 1088)        // union region
#define SEG_  SU_                  //   seg products: 12 slots * 4 rows * 16 g float4 = 3072 floats
#define SBND_ (SU_ + 3072)         //   boundaries: 32 float4 = 128 floats
#define SB_   SU_                  //   B (after phase 2): [64*68] = 4352 floats
#define SMEMF (SU_ + 4352)         // 10624 floats = 42496 B

__device__ __forceinline__ float nan0(float h) {
    unsigned u = __float_as_uint(h);
    return ((u & 0x7fffffffu) > 0x7f800000u) ? 0.0f : h;
}

// build 4x4 M (row-major, 16 floats) for position nn from A-layout at Ab
#define BUILD(Ab, nn, Mar)                                                     \
{                                                                              \
    float xr_ = sm[SXX_ + (nn) * 17 + g];                                      \
    float xi_ = sm[SXY_ + (nn) * 17 + g];                                      \
    const float4* ap_ = (const float4*)((Ab) + (nn) * 32);                     \
    _Pragma("unroll")                                                          \
    for (int q_ = 0; q_ < 8; ++q_) {                                           \
        float4 f_ = ap_[q_];                                                   \
        Mar[2*q_]   = fmaf(f_.x, xr_, f_.y * xi_);                             \
        Mar[2*q_+1] = fmaf(f_.z, xr_, f_.w * xi_);                             \
    }                                                                          \
}

// d = v (row) * M (row-major array of 16)
#define VMATA(d, v_, M)                                                        \
    d.x = fmaf(v_.x, M[0], v_.y * M[4])  + fmaf(v_.z, M[8],  v_.w * M[12]);    \
    d.y = fmaf(v_.x, M[1], v_.y * M[5])  + fmaf(v_.z, M[9],  v_.w * M[13]);    \
    d.z = fmaf(v_.x, M[2], v_.y * M[6])  + fmaf(v_.z, M[10], v_.w * M[14]);    \
    d.w = fmaf(v_.x, M[3], v_.y * M[7])  + fmaf(v_.z, M[11], v_.w * M[15]);

// d = v (row) * [R0;R1;R2;R3]
#define VMAT4(d, v_, R0, R1, R2, R3)                                           \
    d.x = fmaf(v_.x, R0.x, v_.y * R1.x) + fmaf(v_.z, R2.x, v_.w * R3.x);       \
    d.y = fmaf(v_.x, R0.y, v_.y * R1.y) + fmaf(v_.z, R2.y, v_.w * R3.y);       \
    d.z = fmaf(v_.x, R0.z, v_.y * R1.z) + fmaf(v_.z, R2.z, v_.w * R3.z);       \
    d.w = fmaf(v_.x, R0.w, v_.y * R1.w) + fmaf(v_.z, R2.w, v_.w * R3.w);

__global__ __launch_bounds__(TB, 5)
void tdvp_kernel(const float* __restrict__ xg, const float* __restrict__ Ag,
                 const float* __restrict__ Bg, const float* __restrict__ sg,
                 float* __restrict__ yg)
{
    extern __shared__ float sm[];
    const int tid = threadIdx.x;
    const int b0  = blockIdx.x * G;

    // ---- stage A (plus transposed copy) and normalized x ----
    for (int i = tid; i < NN * 32; i += TB) {
        float a = Ag[i];
        sm[SA_ + i] = a;
        int n = i >> 5, rem = i & 31;
        int l = rem >> 3, rr = (rem >> 1) & 3, c = i & 1;
        sm[SAT_ + n * 32 + (rr * 4 + l) * 2 + c] = a;
    }
    const float2* xv = (const float2*)xg;
    for (int idx = tid; idx < G * NN; idx += TB) {
        float2 v = xv[(size_t)b0 * NN + idx];
        float inv = rsqrtf(v.x * v.x + v.y * v.y);
        int bl = idx >> 6, n = idx & 63;
        sm[SXX_ + n * 17 + bl] = v.x * inv;
        sm[SXY_ + n * 17 + bl] = v.y * inv;
    }
    __syncthreads();

    const int g   = tid & 15;       // batch lane
    const int rho = tid >> 4;       // role 0..15
    const bool bwd = rho >= 8;
    const int sub = rho & 7;        // role within direction
    const int b   = b0 + g;
    const float* Ab = bwd ? (sm + SAT_) : (sm + SA_);
    float4* seg = (float4*)(sm + SEG_);
    float4* bnd = (float4*)(sm + SBND_);

    // unified vector rewalk: idx pre-increments by stp, store at idx+stp-offset == idx+stp? no:
    // store position n = idx + stp_dir_offset; here noff == stp.
    auto rewalk = [&](int idx, int stp, float4 v, int trips, float4* gvp) -> float4 {
        #pragma unroll 1
        for (int k = 0; k < trips; ++k) {
            idx += stp;
            float M[16];
            BUILD(Ab, idx, M);
            float4 t; VMATA(t, v, M);
            v = t;
            float d  = v.x*v.x + v.y*v.y + v.z*v.z + v.w*v.w;
            float iv = 1.0f / (sqrtf(d) + 1e-6f);
            gvp[(idx + stp) * BT + b] =
                make_float4(v.x*iv, v.y*iv, v.z*iv, v.w*iv);
        }
        return v;
    };
    // NOTE on store index: fwd (stp=+1): after building M[idx], v = vL_raw(idx+1) -> n = idx+1 ✓
    //                      bwd (stp=-1): after building M'[idx], v = t_raw(idx-1) -> n = idx-1 ✓

    // ================= phase 1 =================
    if (sub <= 5) {
        // segment product: fwd j=sub+1: P_j = M[8j..8j+7] (ascending)
        //                  bwd j=sub+1: Q'_j = M'[8j+7..8j] (descending)
        const int j   = sub + 1;
        int idx       = bwd ? 8*j + 7 : 8*j;
        const int stp = bwd ? -1 : 1;
        const int slot = bwd ? 5 + j : j - 1;          // fwd 0..5, bwd 6..11
        float P[16];
        BUILD(Ab, idx, P);
        #pragma unroll 1
        for (int k = 1; k < 8; ++k) {
            idx += stp;
            float M[16];
            BUILD(Ab, idx, M);
            #pragma unroll
            for (int r2 = 0; r2 < 4; ++r2) {
                float a0 = P[r2*4], a1 = P[r2*4+1], a2 = P[r2*4+2], a3 = P[r2*4+3];
                P[r2*4+0] = fmaf(a0, M[0], a1*M[4])  + fmaf(a2, M[8],  a3*M[12]);
                P[r2*4+1] = fmaf(a0, M[1], a1*M[5])  + fmaf(a2, M[9],  a3*M[13]);
                P[r2*4+2] = fmaf(a0, M[2], a1*M[6])  + fmaf(a2, M[10], a3*M[14]);
                P[r2*4+3] = fmaf(a0, M[3], a1*M[7])  + fmaf(a2, M[11], a3*M[15]);
            }
        }
        #pragma unroll
        for (int c = 0; c < 4; ++c)
            seg[(slot*4 + c)*16 + g] =
                make_float4(P[4*c], P[4*c+1], P[4*c+2], P[4*c+3]);
    } else if (sub == 6) {
        // walker: fwd stores n=1..8 (raw q8 boundary); bwd stores n=62..55 (raw t55 boundary)
        float4 v = rewalk(bwd ? 64 : -1, bwd ? -1 : 1,
                          make_float4(1.f, 0.f, 0.f, 0.f), 8,
                          bwd ? gvR : gvL);
        bnd[(bwd ? 16 : 0) + g] = v;
    }
    __syncthreads();

    // ================= phase 2 =================
    if (sub != 7) {
        // fwd: role sub -> segment s = sub+1 (n = 8s+1..8s+8; s=7 -> 57..63)
        // bwd: role sub -> segment s = sub   (n = 8s..8s+7)
        const int s = bwd ? sub : sub + 1;
        float4 v = bnd[(bwd ? 16 : 0) + g];
        const int cnt   = bwd ? 6 - s : s - 1;
        int jslot       = bwd ? 11 : 0;
        const int jstep = bwd ? -1 : 1;
        #pragma unroll 1
        for (int c = 0; c < cnt; ++c) {
            float4 R0 = seg[(jslot*4 + 0)*16 + g];
            float4 R1 = seg[(jslot*4 + 1)*16 + g];
            float4 R2 = seg[(jslot*4 + 2)*16 + g];
            float4 R3 = seg[(jslot*4 + 3)*16 + g];
            float4 t; VMAT4(t, v, R0, R1, R2, R3);
            v = t;
            jslot += jstep;
        }
        if (bwd) {
            // boundary is vR_raw(8s+7): store it, then walk n = 8s+6 .. 8s
            float d  = v.x*v.x + v.y*v.y + v.z*v.z + v.w*v.w;
            float iv = 1.0f / (sqrtf(d) + 1e-6f);
            gvR[(8*s + 7) * BT + b] = make_float4(v.x*iv, v.y*iv, v.z*iv, v.w*iv);
            rewalk(8*s + 8, -1, v, 7, gvR);
        } else {
            rewalk(8*s - 1, 1, v, (s == 7) ? 7 : 8, gvL);
        }
    }
    __syncthreads();

    // ---- load B into union region (seg products dead now) ----
    for (int i = tid; i < NN * 64; i += TB)
        sm[SB_ + (i >> 6) * 68 + (i & 63)] = Bg[i];
    __syncthreads();

    // ================= output phase: n = rho*4 + k =================
    {
        const float sc = sg[0];
        #pragma unroll 1
        for (int k = 0; k < 4; ++k) {
            const int n = rho * 4 + k;

            float4 u = (n == 0)      ? make_float4(1.f,0.f,0.f,0.f) : gvL[n * BT + b];
            float4 a = (n == NN - 1) ? make_float4(1.f,0.f,0.f,0.f) : gvR[n * BT + b];

            float uu[4] = {u.x, u.y, u.z, u.w};
            float aa[4] = {a.x, a.y, a.z, a.w};
            float H0 = 0.f, H1 = 0.f, H2 = 0.f, H3 = 0.f;
            const float* bb = sm + SB_ + n * 68;
            #pragma unroll
            for (int i2 = 0; i2 < 4; ++i2) {
                #pragma unroll
                for (int l2 = 0; l2 < 4; ++l2) {
                    float w = uu[i2] * aa[l2];
                    float4 bvv = *(const float4*)(bb + i2 * 16 + l2 * 4);
                    H0 = fmaf(w, bvv.x, H0);
                    H1 = fmaf(w, bvv.y, H1);
                    H2 = fmaf(w, bvv.z, H2);
                    H3 = fmaf(w, bvv.w, H3);
                }
            }

            float f    = sqrtf(H0*H0 + H1*H1 + H2*H2 + H3*H3);
            float invf = sc / (f + 1e-6f);
            H0 = fmaxf(nan0(H0 * invf), 0.f);
            H1 = fmaxf(nan0(H1 * invf), 0.f);
            H2 = fmaxf(nan0(H2 * invf), 0.f);
            H3 = fmaxf(nan0(H3 * invf), 0.f);

            float xr = sm[SXX_ + n * 17 + g];
            float xi = sm[SXY_ + n * 17 + g];
            float y0 = fmaf(H0, xr, H1 * xi);
            float y1 = fmaf(H2, xr, H3 * xi);
            sm[SXX_ + n * 17 + g] = y0;     // stash y for coalesced writeback
            sm[SXY_ + n * 17 + g] = y1;
        }
    }
    __syncthreads();

    // ---- coalesced writeback ----
    float2* yv = (float2*)yg;
    for (int idx = tid; idx < G * NN; idx += TB) {
        int bl = idx >> 6, n = idx & 63;
        yv[(size_t)b0 * NN + idx] =
            make_float2(sm[SXX_ + n * 17 + bl], sm[SXY_ + n * 17 + bl]);
    }
}

extern "C" void kernel_launch(void* const* d_in, const int* in_sizes, int n_in,
                              void* d_out, int out_size) {
    const float* x = (const float*)d_in[0];
    const float* A = (const float*)d_in[1];
    const float* B = (const float*)d_in[2];
    const float* s = (const float*)d_in[3];
    float* y = (float*)d_out;

    const int batch = in_sizes[0] / (NN * 2);   // 16384
    const int grid  = batch / G;                // 1024
    const size_t smem = (size_t)SMEMF * sizeof(float);

    cudaFuncSetAttribute(tdvp_kernel, cudaFuncAttributeMaxDynamicSharedMemorySize, (int)smem);
    tdvp_kernel<<<grid, TB, smem>>>(x, A, B, s, y);
}

// round 10
// speedup vs baseline: 1.3801x; 1.0315x over previous
#include <cuda_runtime.h>
#include <cstddef>

#define NN 64
#define G  16          // batches per block (half-warp lanes)
#define TB 256         // 16 half-warp roles
#define BT 16384       // total batches

// global scratch (L2-resident), coalesced [n][b]
__device__ float4 gvL[NN * BT];   // normalized prefix vectors, n = 1..63
__device__ float4 gvR[NN * BT];   // normalized suffix vectors, n = 0..62

// smem float offsets
#define SA_   0                    // A [64*32]                 = 2048
#define SXX_  2048                 // xn.x [64*17]              = 1088
#define SXY_  (SXX_ + 1088)        // xn.y [64*17]              = 1088
#define SU_   (SXY_ + 1088)        // union region
#define SEG_  SU_                  //   12 half-prods * 4 rows * 16 g float4 = 3072 floats
#define SBND_ (SU_ + 3072)         //   boundaries: 32 float4 = 128 floats
#define SB_   SU_                  //   B (after phase 2): [64*64] = 4096 floats
#define SMEMF (SU_ + 4096)         // 8320 floats = 33280 B

__device__ __forceinline__ float nan0(float h) {
    unsigned u = __float_as_uint(h);
    return ((u & 0x7fffffffu) > 0x7f800000u) ? 0.0f : h;
}

// build 4x4 M (row-major, 16 floats) for position nn
#define BUILD(nn, Mar)                                                         \
{                                                                              \
    float xr_ = sm[SXX_ + (nn) * 17 + g];                                      \
    float xi_ = sm[SXY_ + (nn) * 17 + g];                                      \
    const float4* ap_ = (const float4*)(sm + SA_ + (nn) * 32);                 \
    _Pragma("unroll")                                                          \
    for (int q_ = 0; q_ < 8; ++q_) {                                           \
        float4 f_ = ap_[q_];                                                   \
        Mar[2*q_]   = fmaf(f_.x, xr_, f_.y * xi_);                             \
        Mar[2*q_+1] = fmaf(f_.z, xr_, f_.w * xi_);                             \
    }                                                                          \
}

// d = v (row) * M (row-major 16)
#define VMATA(d, v_, M)                                                        \
    d.x = fmaf(v_.x, M[0], v_.y * M[4])  + fmaf(v_.z, M[8],  v_.w * M[12]);    \
    d.y = fmaf(v_.x, M[1], v_.y * M[5])  + fmaf(v_.z, M[9],  v_.w * M[13]);    \
    d.z = fmaf(v_.x, M[2], v_.y * M[6])  + fmaf(v_.z, M[10], v_.w * M[14]);    \
    d.w = fmaf(v_.x, M[3], v_.y * M[7])  + fmaf(v_.z, M[11], v_.w * M[15]);

// d = M (row-major 16) * w (column)
#define MATVA(d, M, w_)                                                        \
    d.x = fmaf(M[0],  w_.x, M[1]  * w_.y) + fmaf(M[2],  w_.z, M[3]  * w_.w);   \
    d.y = fmaf(M[4],  w_.x, M[5]  * w_.y) + fmaf(M[6],  w_.z, M[7]  * w_.w);   \
    d.z = fmaf(M[8],  w_.x, M[9]  * w_.y) + fmaf(M[10], w_.z, M[11] * w_.w);   \
    d.w = fmaf(M[12], w_.x, M[13] * w_.y) + fmaf(M[14], w_.z, M[15] * w_.w);

// d = v (row) * [R0;R1;R2;R3]
#define VMAT4(d, v_, R0, R1, R2, R3)                                           \
    d.x = fmaf(v_.x, R0.x, v_.y * R1.x) + fmaf(v_.z, R2.x, v_.w * R3.x);       \
    d.y = fmaf(v_.x, R0.y, v_.y * R1.y) + fmaf(v_.z, R2.y, v_.w * R3.y);       \
    d.z = fmaf(v_.x, R0.z, v_.y * R1.z) + fmaf(v_.z, R2.z, v_.w * R3.z);       \
    d.w = fmaf(v_.x, R0.w, v_.y * R1.w) + fmaf(v_.z, R2.w, v_.w * R3.w);

// d = [R0;R1;R2;R3] * w (column)
#define MATV4(d, R0, R1, R2, R3, w_)                                           \
    d.x = fmaf(R0.x, w_.x, R0.y * w_.y) + fmaf(R0.z, w_.z, R0.w * w_.w);       \
    d.y = fmaf(R1.x, w_.x, R1.y * w_.y) + fmaf(R1.z, w_.z, R1.w * w_.w);       \
    d.z = fmaf(R2.x, w_.x, R2.y * w_.y) + fmaf(R2.z, w_.z, R2.w * w_.w);       \
    d.w = fmaf(R3.x, w_.x, R3.y * w_.y) + fmaf(R3.z, w_.z, R3.w * w_.w);

__global__ __launch_bounds__(TB, 6)
void tdvp_kernel(const float* __restrict__ xg, const float* __restrict__ Ag,
                 const float* __restrict__ Bg, const float* __restrict__ sg,
                 float* __restrict__ yg)
{
    extern __shared__ float sm[];
    const int tid = threadIdx.x;
    const int b0  = blockIdx.x * G;

    for (int i = tid; i < NN * 32; i += TB) sm[SA_ + i] = Ag[i];
    const float2* xv = (const float2*)xg;
    for (int idx = tid; idx < G * NN; idx += TB) {
        float2 v = xv[(size_t)b0 * NN + idx];
        float inv = rsqrtf(v.x * v.x + v.y * v.y);
        int bl = idx >> 6, n = idx & 63;
        sm[SXX_ + n * 17 + bl] = v.x * inv;
        sm[SXY_ + n * 17 + bl] = v.y * inv;
    }
    __syncthreads();

    const int g   = tid & 15;       // batch lane
    const int rho = tid >> 4;       // role 0..15
    const int b   = b0 + g;
    float4* seg = (float4*)(sm + SEG_);
    float4* bnd = (float4*)(sm + SBND_);

    // fwd walk: build M[idx0+k], v <- v*M, store normalized gvL[idx0+k+1]
    auto fwalk = [&](int idx0, float4 v, int trips) -> float4 {
        #pragma unroll 1
        for (int k = 0; k < trips; ++k) {
            float M[16];
            BUILD(idx0 + k, M);
            float4 t; VMATA(t, v, M);
            v = t;
            float d  = v.x*v.x + v.y*v.y + v.z*v.z + v.w*v.w;
            float iv = 1.0f / (sqrtf(d) + 1e-6f);
            gvL[(idx0 + k + 1) * BT + b] = make_float4(v.x*iv, v.y*iv, v.z*iv, v.w*iv);
        }
        return v;
    };
    // bwd walk: build M[idx0-k], w <- M*w, store normalized gvR[idx0-k-1]
    auto bwalk = [&](int idx0, float4 w, int trips) -> float4 {
        #pragma unroll 1
        for (int k = 0; k < trips; ++k) {
            float M[16];
            BUILD(idx0 - k, M);
            float4 t; MATVA(t, M, w);
            w = t;
            float d  = w.x*w.x + w.y*w.y + w.z*w.z + w.w*w.w;
            float iv = 1.0f / (sqrtf(d) + 1e-6f);
            gvR[(idx0 - k - 1) * BT + b] = make_float4(w.x*iv, w.y*iv, w.z*iv, w.w*iv);
        }
        return w;
    };

    // ================= phase 1: shared half-products + walkers =================
    if (rho < 12) {
        // H_{j,half} : half 0 = M[8j..8j+3], half 1 = M[8j+4..8j+7], j = 1..6
        const int half = (rho >= 6);
        const int j    = half ? rho - 5 : rho + 1;
        const int base = 8 * j + 4 * half;
        float P[16];
        BUILD(base, P);
        #pragma unroll 1
        for (int k = 1; k < 4; ++k) {
            float M[16];
            BUILD(base + k, M);
            #pragma unroll
            for (int r2 = 0; r2 < 4; ++r2) {
                float a0 = P[r2*4], a1 = P[r2*4+1], a2 = P[r2*4+2], a3 = P[r2*4+3];
                P[r2*4+0] = fmaf(a0, M[0], a1*M[4])  + fmaf(a2, M[8],  a3*M[12]);
                P[r2*4+1] = fmaf(a0, M[1], a1*M[5])  + fmaf(a2, M[9],  a3*M[13]);
                P[r2*4+2] = fmaf(a0, M[2], a1*M[6])  + fmaf(a2, M[10], a3*M[14]);
                P[r2*4+3] = fmaf(a0, M[3], a1*M[7])  + fmaf(a2, M[11], a3*M[15]);
            }
        }
        const int slot = (j - 1) * 2 + half;
        #pragma unroll
        for (int c = 0; c < 4; ++c)
            seg[(slot*4 + c)*16 + g] = make_float4(P[4*c], P[4*c+1], P[4*c+2], P[4*c+3]);
    } else if (rho == 12) {
        // fwd walker: stores n = 1..8, boundary raw q8
        float4 v = fwalk(0, make_float4(1.f, 0.f, 0.f, 0.f), 8);
        bnd[g] = v;
    } else if (rho == 14) {
        // bwd walker: stores n = 62..55, boundary raw t55
        float4 w = bwalk(63, make_float4(1.f, 0.f, 0.f, 0.f), 8);
        bnd[16 + g] = w;
    }
    __syncthreads();

    // ================= phase 2: boundary chains over shared halves + rewalk =================
    if (rho <= 6) {
        // fwd segment s = rho+1: n = 8s+1 .. 8s+8 (s=7 -> 57..63)
        const int s = rho + 1;
        float4 v = bnd[g];                       // raw q8
        #pragma unroll 1
        for (int slot = 0; slot < 2 * (s - 1); ++slot) {
            float4 R0 = seg[(slot*4 + 0)*16 + g];
            float4 R1 = seg[(slot*4 + 1)*16 + g];
            float4 R2 = seg[(slot*4 + 2)*16 + g];
            float4 R3 = seg[(slot*4 + 3)*16 + g];
            float4 t; VMAT4(t, v, R0, R1, R2, R3);
            v = t;
        }
        fwalk(8 * s, v, (s == 7) ? 7 : 8);
    } else if (rho >= 8 && rho <= 14) {
        // bwd segment s = rho-8 (0..6): boundary t(8s+7), then n = 8s+6 .. 8s
        const int s = rho - 8;
        float4 w = bnd[16 + g];                  // raw t55
        #pragma unroll 1
        for (int slot = 13 - (13 - 2 * (6 - s)); slot <= 13; ++slot) { /* placeholder */ }
        // apply halves j = 6 down to s+1, hi then lo:
        #pragma unroll 1
        for (int j = 6; j > s; --j) {
            #pragma unroll
            for (int half = 1; half >= 0; --half) {
                const int slot = (j - 1) * 2 + half;
                float4 R0 = seg[(slot*4 + 0)*16 + g];
                float4 R1 = seg[(slot*4 + 1)*16 + g];
                float4 R2 = seg[(slot*4 + 2)*16 + g];
                float4 R3 = seg[(slot*4 + 3)*16 + g];
                float4 t; MATV4(t, R0, R1, R2, R3, w);
                w = t;
            }
        }
        {   // store normalized t(8s+7)
            float d  = w.x*w.x + w.y*w.y + w.z*w.z + w.w*w.w;
            float iv = 1.0f / (sqrtf(d) + 1e-6f);
            gvR[(8*s + 7) * BT + b] = make_float4(w.x*iv, w.y*iv, w.z*iv, w.w*iv);
        }
        bwalk(8 * s + 7, w, 7);
    }
    __syncthreads();

    // ---- load B into union region (seg products dead now) ----
    for (int i = tid; i < NN * 64; i += TB) sm[SB_ + i] = Bg[i];
    __syncthreads();

    // ================= output phase: n = rho*4 + k =================
    {
        const float sc = sg[0];
        #pragma unroll 1
        for (int k = 0; k < 4; ++k) {
            const int n = rho * 4 + k;

            float4 u = (n == 0)      ? make_float4(1.f,0.f,0.f,0.f) : gvL[n * BT + b];
            float4 a = (n == NN - 1) ? make_float4(1.f,0.f,0.f,0.f) : gvR[n * BT + b];

            float uu[4] = {u.x, u.y, u.z, u.w};
            float aa[4] = {a.x, a.y, a.z, a.w};
            float H0 = 0.f, H1 = 0.f, H2 = 0.f, H3 = 0.f;
            const float* bb = sm + SB_ + n * 64;
            #pragma unroll
            for (int i2 = 0; i2 < 4; ++i2) {
                #pragma unroll
                for (int l2 = 0; l2 < 4; ++l2) {
                    float w = uu[i2] * aa[l2];
                    float4 bvv = *(const float4*)(bb + i2 * 16 + l2 * 4);  // broadcast
                    H0 = fmaf(w, bvv.x, H0);
                    H1 = fmaf(w, bvv.y, H1);
                    H2 = fmaf(w, bvv.z, H2);
                    H3 = fmaf(w, bvv.w, H3);
                }
            }

            float f    = sqrtf(H0*H0 + H1*H1 + H2*H2 + H3*H3);
            float invf = sc / (f + 1e-6f);
            H0 = fmaxf(nan0(H0 * invf), 0.f);
            H1 = fmaxf(nan0(H1 * invf), 0.f);
            H2 = fmaxf(nan0(H2 * invf), 0.f);
            H3 = fmaxf(nan0(H3 * invf), 0.f);

            float xr = sm[SXX_ + n * 17 + g];
            float xi = sm[SXY_ + n * 17 + g];
            float y0 = fmaf(H0, xr, H1 * xi);
            float y1 = fmaf(H2, xr, H3 * xi);
            sm[SXX_ + n * 17 + g] = y0;
            sm[SXY_ + n * 17 + g] = y1;
        }
    }
    __syncthreads();

    // ---- coalesced writeback ----
    float2* yv = (float2*)yg;
    for (int idx = tid; idx < G * NN; idx += TB) {
        int bl = idx >> 6, n = idx & 63;
        yv[(size_t)b0 * NN + idx] =
            make_float2(sm[SXX_ + n * 17 + bl], sm[SXY_ + n * 17 + bl]);
    }
}

extern "C" void kernel_launch(void* const* d_in, const int* in_sizes, int n_in,
                              void* d_out, int out_size) {
    const float* x = (const float*)d_in[0];
    const float* A = (const float*)d_in[1];
    const float* B = (const float*)d_in[2];
    const float* s = (const float*)d_in[3];
    float* y = (float*)d_out;

    const int batch = in_sizes[0] / (NN * 2);   // 16384
    const int grid  = batch / G;                // 1024
    const size_t smem = (size_t)SMEMF * sizeof(float);

    cudaFuncSetAttribute(tdvp_kernel, cudaFuncAttributeMaxDynamicSharedMemorySize, (int)smem);
    tdvp_kernel<<<grid, TB, smem>>>(x, A, B, s, y);
}